// round 4
// baseline (speedup 1.0000x reference)
#include <cuda_runtime.h>
#include <cmath>

#define NN 8192
#define NB1 32
#define IBLK 8
#define ICH (NN/IBLK)      /* 1024 */
#define JBLK 16
#define JPB (NN/JBLK)      /* 512  */
#define KC4 512

typedef unsigned long long ull;

// ---------------- scratch (__device__ globals: no allocs allowed) ----------------
__device__ __align__(16) float4 g_XeT[NN];
__device__ __align__(16) float4 g_SeT[NN];
__device__ float g_bmax[NB1];
__device__ __align__(16) float4 g_pnum[2][IBLK][NN];
__device__ float g_pden[2][IBLK][NN];
__device__ __align__(16) float g_Xa[4*NN];
__device__ __align__(16) float g_Sa[4*NN];
__device__ __align__(16) float g_Mx[4*NN];
__device__ __align__(16) float g_Ms[4*NN];

// ---------------- small PTX helpers ----------------
__device__ __forceinline__ ull pk2(float lo, float hi){ ull r; asm("mov.b64 %0, {%1, %2};" : "=l"(r) : "f"(lo), "f"(hi)); return r; }
__device__ __forceinline__ float2 upk2(ull v){ float2 f; asm("mov.b64 {%0, %1}, %2;" : "=f"(f.x), "=f"(f.y) : "l"(v)); return f; }
__device__ __forceinline__ ull fma2(ull a, ull b, ull c){ ull d; asm("fma.rn.f32x2 %0, %1, %2, %3;" : "=l"(d) : "l"(a), "l"(b), "l"(c)); return d; }
__device__ __forceinline__ ull add2(ull a, ull b){ ull d; asm("add.rn.f32x2 %0, %1, %2;" : "=l"(d) : "l"(a), "l"(b)); return d; }
__device__ __forceinline__ ull ex2pair(ull g){
  ull e;
  asm("{\n\t.reg .f32 lo, hi;\n\t"
      "mov.b64 {lo, hi}, %1;\n\t"
      "ex2.approx.ftz.f32 lo, lo;\n\t"
      "ex2.approx.ftz.f32 hi, hi;\n\t"
      "mov.b64 %0, {lo, hi};\n\t}" : "=l"(e) : "l"(g));
  return e;
}

// ---------------- k1: Xe = W1x@S, Se = W1s@X, per-column norms, block max ----------------
__global__ void k1_embed(const float* __restrict__ X, const float* __restrict__ S,
                         const float* __restrict__ W1x, const float* __restrict__ W1s){
  int j = blockIdx.x*blockDim.x + threadIdx.x;
  float s0=S[j], s1=S[NN+j], s2=S[2*NN+j], s3=S[3*NN+j];
  float x0=X[j], x1=X[NN+j], x2=X[2*NN+j], x3=X[3*NN+j];
  float4 xe, se;
  xe.x = W1x[ 0]*s0 + W1x[ 1]*s1 + W1x[ 2]*s2 + W1x[ 3]*s3;
  xe.y = W1x[ 4]*s0 + W1x[ 5]*s1 + W1x[ 6]*s2 + W1x[ 7]*s3;
  xe.z = W1x[ 8]*s0 + W1x[ 9]*s1 + W1x[10]*s2 + W1x[11]*s3;
  xe.w = W1x[12]*s0 + W1x[13]*s1 + W1x[14]*s2 + W1x[15]*s3;
  se.x = W1s[ 0]*x0 + W1s[ 1]*x1 + W1s[ 2]*x2 + W1s[ 3]*x3;
  se.y = W1s[ 4]*x0 + W1s[ 5]*x1 + W1s[ 6]*x2 + W1s[ 7]*x3;
  se.z = W1s[ 8]*x0 + W1s[ 9]*x1 + W1s[10]*x2 + W1s[11]*x3;
  se.w = W1s[12]*x0 + W1s[13]*x1 + W1s[14]*x2 + W1s[15]*x3;
  g_XeT[j] = xe; g_SeT[j] = se;
  float nx = xe.x*xe.x + xe.y*xe.y + xe.z*xe.z + xe.w*xe.w;
  float ns = se.x*se.x + se.y*se.y + se.z*se.z + se.w*se.w;
  float m = sqrtf(fmaxf(nx, ns));
  __shared__ float red[256];
  red[threadIdx.x] = m; __syncthreads();
  for (int s = 128; s > 0; s >>= 1){
    if (threadIdx.x < s) red[threadIdx.x] = fmaxf(red[threadIdx.x], red[threadIdx.x+s]);
    __syncthreads();
  }
  if (threadIdx.x == 0) g_bmax[blockIdx.x] = red[0];
}

// ---------------- k2: rank-4 streaming softmax-attention partials (f32x2 over i-pairs) ----------------
__global__ void k2_attn(){
  const int jb = blockIdx.x, ib = blockIdx.y, br = blockIdx.z;
  const float4* __restrict__ E = br ? g_SeT : g_XeT;
  __shared__ float shX[ICH], shY[ICH], shZ[ICH], shW[ICH];

  float Nmax = 0.f;
  #pragma unroll
  for (int b = 0; b < NB1; b++) Nmax = fmaxf(Nmax, g_bmax[b]);

  const int ibase = ib*ICH;
  for (int t = threadIdx.x; t < ICH; t += blockDim.x){
    float4 v = E[ibase + t];
    shX[t]=v.x; shY[t]=v.y; shZ[t]=v.z; shW[t]=v.w;
  }
  __syncthreads();

  const float L2E = 1.4426950408889634f;
  const int j0 = jb*JPB + threadIdx.x;
  const int j1 = j0 + 256;
  float4 q0 = E[j0], q1 = E[j1];
  float c0 = sqrtf(q0.x*q0.x+q0.y*q0.y+q0.z*q0.z+q0.w*q0.w) * Nmax * L2E;
  float c1 = sqrtf(q1.x*q1.x+q1.y*q1.y+q1.z*q1.z+q1.w*q1.w) * Nmax * L2E;
  ull qx0 = pk2(q0.x*L2E, q0.x*L2E), qy0 = pk2(q0.y*L2E, q0.y*L2E);
  ull qz0 = pk2(q0.z*L2E, q0.z*L2E), qw0 = pk2(q0.w*L2E, q0.w*L2E);
  ull qx1 = pk2(q1.x*L2E, q1.x*L2E), qy1 = pk2(q1.y*L2E, q1.y*L2E);
  ull qz1 = pk2(q1.z*L2E, q1.z*L2E), qw1 = pk2(q1.w*L2E, q1.w*L2E);
  ull cc0 = pk2(-c0, -c0), cc1 = pk2(-c1, -c1);

  ull d0 = 0ull, d1 = 0ull;
  ull n0x=0ull, n0y=0ull, n0z=0ull, n0w=0ull;
  ull n1x=0ull, n1y=0ull, n1z=0ull, n1w=0ull;

  const ull* sX = (const ull*)shX; const ull* sY = (const ull*)shY;
  const ull* sZ = (const ull*)shZ; const ull* sW = (const ull*)shW;

  #pragma unroll 4
  for (int ii = 0; ii < ICH/2; ii++){
    ull sx = sX[ii], sy = sY[ii], sz = sZ[ii], sw = sW[ii];
    ull g0 = fma2(qx0, sx, fma2(qy0, sy, fma2(qz0, sz, fma2(qw0, sw, cc0))));
    ull e0 = ex2pair(g0);
    d0  = add2(d0, e0);
    n0x = fma2(sx, e0, n0x); n0y = fma2(sy, e0, n0y);
    n0z = fma2(sz, e0, n0z); n0w = fma2(sw, e0, n0w);
    ull g1 = fma2(qx1, sx, fma2(qy1, sy, fma2(qz1, sz, fma2(qw1, sw, cc1))));
    ull e1 = ex2pair(g1);
    d1  = add2(d1, e1);
    n1x = fma2(sx, e1, n1x); n1y = fma2(sy, e1, n1y);
    n1z = fma2(sz, e1, n1z); n1w = fma2(sw, e1, n1w);
  }

  float2 t2; float4 p;
  t2 = upk2(n0x); p.x = t2.x + t2.y;
  t2 = upk2(n0y); p.y = t2.x + t2.y;
  t2 = upk2(n0z); p.z = t2.x + t2.y;
  t2 = upk2(n0w); p.w = t2.x + t2.y;
  g_pnum[br][ib][j0] = p;
  t2 = upk2(d0);  g_pden[br][ib][j0] = t2.x + t2.y;

  t2 = upk2(n1x); p.x = t2.x + t2.y;
  t2 = upk2(n1y); p.y = t2.x + t2.y;
  t2 = upk2(n1z); p.z = t2.x + t2.y;
  t2 = upk2(n1w); p.w = t2.x + t2.y;
  g_pnum[br][ib][j1] = p;
  t2 = upk2(d1);  g_pden[br][ib][j1] = t2.x + t2.y;
}

// ---------------- k3: combine partials -> Xa, Sa ----------------
__global__ void k3_combine(){
  int idx = blockIdx.x*256 + threadIdx.x;      // 0..16383
  int br = idx >> 13; int j = idx & (NN-1);
  float4 n = make_float4(0.f,0.f,0.f,0.f); float d = 0.f;
  #pragma unroll
  for (int ib = 0; ib < IBLK; ib++){
    float4 p = g_pnum[br][ib][j];
    n.x += p.x; n.y += p.y; n.z += p.z; n.w += p.w;
    d += g_pden[br][ib][j];
  }
  float inv = 1.0f / d;
  float* out = br ? g_Sa : g_Xa;
  out[0*NN+j] = n.x*inv; out[1*NN+j] = n.y*inv;
  out[2*NN+j] = n.z*inv; out[3*NN+j] = n.w*inv;
}

// ---------------- k4: M = W2 (8192x8192) @ C (8192x8); 2 rows/warp, 4 blocks/SM ----------------
__global__ void __launch_bounds__(256, 4) k4_gemv(const float* __restrict__ W2){
  __shared__ __align__(16) float Cs[8][KC4];
  const int warp = threadIdx.x >> 5, lane = threadIdx.x & 31;
  const int r0 = blockIdx.x*16 + warp*2;     // this warp's 2 rows
  ull acc[2][8];
  #pragma unroll
  for (int r = 0; r < 2; r++)
    #pragma unroll
    for (int c = 0; c < 8; c++) acc[r][c] = 0ull;

  for (int kc = 0; kc < NN; kc += KC4){
    __syncthreads();
    for (int t = threadIdx.x; t < KC4; t += 256){
      float4 a = *(const float4*)&g_Xa[(size_t)(kc + t)*4];
      Cs[0][t]=a.x; Cs[1][t]=a.y; Cs[2][t]=a.z; Cs[3][t]=a.w;
      float4 b = *(const float4*)&g_Sa[(size_t)(kc + t)*4];
      Cs[4][t]=b.x; Cs[5][t]=b.y; Cs[6][t]=b.z; Cs[7][t]=b.w;
    }
    __syncthreads();
    #pragma unroll
    for (int it = 0; it < KC4/128; it++){
      const int kk = it*128 + lane*4;
      float4 a = __ldcs((const float4*)&W2[(size_t)r0*NN + kc + kk]);
      float4 b = __ldcs((const float4*)&W2[(size_t)(r0+1)*NN + kc + kk]);
      ull w00 = pk2(a.x, a.y), w01 = pk2(a.z, a.w);
      ull w10 = pk2(b.x, b.y), w11 = pk2(b.z, b.w);
      #pragma unroll
      for (int c = 0; c < 8; c++){
        ulonglong2 cv = *(const ulonglong2*)&Cs[c][kk];
        acc[0][c] = fma2(w01, cv.y, fma2(w00, cv.x, acc[0][c]));
        acc[1][c] = fma2(w11, cv.y, fma2(w10, cv.x, acc[1][c]));
      }
    }
  }

  #pragma unroll
  for (int o = 0; o < 16; o++){
    int r = o >> 3, c = o & 7;
    float2 t2 = upk2(acc[r][c]);
    float v = t2.x + t2.y;
    v += __shfl_xor_sync(0xffffffffu, v, 16);
    v += __shfl_xor_sync(0xffffffffu, v, 8);
    v += __shfl_xor_sync(0xffffffffu, v, 4);
    v += __shfl_xor_sync(0xffffffffu, v, 2);
    v += __shfl_xor_sync(0xffffffffu, v, 1);
    if (lane == o){
      int row = r0 + r;
      if (c < 4) g_Mx[row*4 + c] = v;
      else       g_Ms[row*4 + (c-4)] = v;
    }
  }
}

// ---------------- k5: gates + sinusoid + dual 3x3(W=1 -> 1D vertical) conv ----------------
__global__ void k5_conv(const float* __restrict__ X, const float* __restrict__ S,
                        const float* __restrict__ wx, const float* __restrict__ bx,
                        const float* __restrict__ ws, const float* __restrict__ bs,
                        float* __restrict__ out){
  __shared__ float in_s[2][8][258];
  __shared__ float wmid[2][8][8][3];
  __shared__ float bias[2][8];
  __shared__ float sins[258];
  const int t = threadIdx.x;
  const int n0 = blockIdx.x*256;

  for (int idx = t; idx < 384; idx += 256){
    int b = idx/192, rem = idx%192;
    int co = rem/24, ci = (rem%24)/3, kh = rem%3;
    const float* w = b ? ws : wx;
    wmid[b][co][ci][kh] = w[((co*8 + ci)*3 + kh)*3 + 1];
  }
  if (t < 16) bias[t>>3][t&7] = (t < 8) ? bx[t] : bs[t-8];
  for (int col = t; col < 258; col += 256)
    sins[col] = (float)sin((double)(n0 + col - 1));
  __syncthreads();

  for (int idx = t; idx < 2*8*258; idx += 256){
    int b = idx/(8*258); int rem = idx%(8*258);
    int ci = rem/258, col = rem%258;
    int n = n0 + col - 1;
    float v = 0.f;
    if (n >= 0 && n < NN){
      if (b == 0){
        v = (ci < 4) ? g_Mx[ci*NN + n]*X[ci*NN + n] : X[(ci-4)*NN + n];
      } else {
        v = (ci < 4) ? g_Ms[ci*NN + n]*X[ci*NN + n] : S[(ci-4)*NN + n];
        v += sins[col];
      }
    }
    in_s[b][ci][col] = v;
  }
  __syncthreads();

  const int n = n0 + t;
  #pragma unroll
  for (int b = 0; b < 2; b++){
    #pragma unroll
    for (int co = 0; co < 8; co++){
      float a = bias[b][co];
      #pragma unroll
      for (int ci = 0; ci < 8; ci++){
        a = fmaf(wmid[b][co][ci][0], in_s[b][ci][t  ], a);
        a = fmaf(wmid[b][co][ci][1], in_s[b][ci][t+1], a);
        a = fmaf(wmid[b][co][ci][2], in_s[b][ci][t+2], a);
      }
      out[(size_t)b*8*NN + (size_t)co*NN + n] = a;
    }
  }
}

// ---------------- launch ----------------
extern "C" void kernel_launch(void* const* d_in, const int* in_sizes, int n_in,
                              void* d_out, int out_size){
  (void)in_sizes; (void)n_in; (void)out_size;
  const float* X   = (const float*)d_in[0];
  const float* S   = (const float*)d_in[1];
  const float* W1x = (const float*)d_in[2];
  const float* W1s = (const float*)d_in[3];
  const float* W2  = (const float*)d_in[4];
  const float* cwx = (const float*)d_in[5];
  const float* cbx = (const float*)d_in[6];
  const float* cws = (const float*)d_in[7];
  const float* cbs = (const float*)d_in[8];
  float* out = (float*)d_out;

  k1_embed  <<<NB1, 256>>>(X, S, W1x, W1s);
  k2_attn   <<<dim3(JBLK, IBLK, 2), 256>>>();
  k3_combine<<<64, 256>>>();
  k4_gemv   <<<NN/16, 256>>>(W2);
  k5_conv   <<<NN/256, 256>>>(X, S, cwx, cbx, cws, cbs, out);
}

// round 5
// speedup vs baseline: 1.0201x; 1.0201x over previous
#include <cuda_runtime.h>
#include <cmath>

#define NN 8192
#define NB1 32
#define IBLK 8
#define ICH (NN/IBLK)      /* 1024 */
#define JBLK 16
#define JPB (NN/JBLK)      /* 512  */
#define KC 1024

typedef unsigned long long ull;

// ---------------- scratch (__device__ globals: no allocs allowed) ----------------
__device__ __align__(16) float4 g_XeT[NN];
__device__ __align__(16) float4 g_SeT[NN];
__device__ float g_bmax[NB1];
__device__ __align__(16) float4 g_pnum[2][IBLK][NN];
__device__ float g_pden[2][IBLK][NN];
__device__ __align__(16) float g_Xa[4*NN];
__device__ __align__(16) float g_Sa[4*NN];
__device__ __align__(16) float g_Mx[4*NN];
__device__ __align__(16) float g_Ms[4*NN];

// ---------------- small PTX helpers ----------------
__device__ __forceinline__ ull pk2(float lo, float hi){ ull r; asm("mov.b64 %0, {%1, %2};" : "=l"(r) : "f"(lo), "f"(hi)); return r; }
__device__ __forceinline__ float2 upk2(ull v){ float2 f; asm("mov.b64 {%0, %1}, %2;" : "=f"(f.x), "=f"(f.y) : "l"(v)); return f; }
__device__ __forceinline__ ull fma2(ull a, ull b, ull c){ ull d; asm("fma.rn.f32x2 %0, %1, %2, %3;" : "=l"(d) : "l"(a), "l"(b), "l"(c)); return d; }
__device__ __forceinline__ ull add2(ull a, ull b){ ull d; asm("add.rn.f32x2 %0, %1, %2;" : "=l"(d) : "l"(a), "l"(b)); return d; }
__device__ __forceinline__ ull ex2pair(ull g){
  ull e;
  asm("{\n\t.reg .f32 lo, hi;\n\t"
      "mov.b64 {lo, hi}, %1;\n\t"
      "ex2.approx.ftz.f32 lo, lo;\n\t"
      "ex2.approx.ftz.f32 hi, hi;\n\t"
      "mov.b64 %0, {lo, hi};\n\t}" : "=l"(e) : "l"(g));
  return e;
}

// ---------------- k1: Xe = W1x@S, Se = W1s@X, per-column norms, block max ----------------
__global__ void k1_embed(const float* __restrict__ X, const float* __restrict__ S,
                         const float* __restrict__ W1x, const float* __restrict__ W1s){
  int j = blockIdx.x*blockDim.x + threadIdx.x;
  float s0=S[j], s1=S[NN+j], s2=S[2*NN+j], s3=S[3*NN+j];
  float x0=X[j], x1=X[NN+j], x2=X[2*NN+j], x3=X[3*NN+j];
  float4 xe, se;
  xe.x = W1x[ 0]*s0 + W1x[ 1]*s1 + W1x[ 2]*s2 + W1x[ 3]*s3;
  xe.y = W1x[ 4]*s0 + W1x[ 5]*s1 + W1x[ 6]*s2 + W1x[ 7]*s3;
  xe.z = W1x[ 8]*s0 + W1x[ 9]*s1 + W1x[10]*s2 + W1x[11]*s3;
  xe.w = W1x[12]*s0 + W1x[13]*s1 + W1x[14]*s2 + W1x[15]*s3;
  se.x = W1s[ 0]*x0 + W1s[ 1]*x1 + W1s[ 2]*x2 + W1s[ 3]*x3;
  se.y = W1s[ 4]*x0 + W1s[ 5]*x1 + W1s[ 6]*x2 + W1s[ 7]*x3;
  se.z = W1s[ 8]*x0 + W1s[ 9]*x1 + W1s[10]*x2 + W1s[11]*x3;
  se.w = W1s[12]*x0 + W1s[13]*x1 + W1s[14]*x2 + W1s[15]*x3;
  g_XeT[j] = xe; g_SeT[j] = se;
  float nx = xe.x*xe.x + xe.y*xe.y + xe.z*xe.z + xe.w*xe.w;
  float ns = se.x*se.x + se.y*se.y + se.z*se.z + se.w*se.w;
  float m = sqrtf(fmaxf(nx, ns));
  __shared__ float red[256];
  red[threadIdx.x] = m; __syncthreads();
  for (int s = 128; s > 0; s >>= 1){
    if (threadIdx.x < s) red[threadIdx.x] = fmaxf(red[threadIdx.x], red[threadIdx.x+s]);
    __syncthreads();
  }
  if (threadIdx.x == 0) g_bmax[blockIdx.x] = red[0];
}

// ---------------- k2: rank-4 streaming softmax-attention partials (f32x2 over i-pairs) ----------------
__global__ void k2_attn(){
  const int jb = blockIdx.x, ib = blockIdx.y, br = blockIdx.z;
  const float4* __restrict__ E = br ? g_SeT : g_XeT;
  __shared__ float shX[ICH], shY[ICH], shZ[ICH], shW[ICH];

  float Nmax = 0.f;
  #pragma unroll
  for (int b = 0; b < NB1; b++) Nmax = fmaxf(Nmax, g_bmax[b]);

  const int ibase = ib*ICH;
  for (int t = threadIdx.x; t < ICH; t += blockDim.x){
    float4 v = E[ibase + t];
    shX[t]=v.x; shY[t]=v.y; shZ[t]=v.z; shW[t]=v.w;
  }
  __syncthreads();

  const float L2E = 1.4426950408889634f;
  const int j0 = jb*JPB + threadIdx.x;
  const int j1 = j0 + 256;
  float4 q0 = E[j0], q1 = E[j1];
  float c0 = sqrtf(q0.x*q0.x+q0.y*q0.y+q0.z*q0.z+q0.w*q0.w) * Nmax * L2E;
  float c1 = sqrtf(q1.x*q1.x+q1.y*q1.y+q1.z*q1.z+q1.w*q1.w) * Nmax * L2E;
  ull qx0 = pk2(q0.x*L2E, q0.x*L2E), qy0 = pk2(q0.y*L2E, q0.y*L2E);
  ull qz0 = pk2(q0.z*L2E, q0.z*L2E), qw0 = pk2(q0.w*L2E, q0.w*L2E);
  ull qx1 = pk2(q1.x*L2E, q1.x*L2E), qy1 = pk2(q1.y*L2E, q1.y*L2E);
  ull qz1 = pk2(q1.z*L2E, q1.z*L2E), qw1 = pk2(q1.w*L2E, q1.w*L2E);
  ull cc0 = pk2(-c0, -c0), cc1 = pk2(-c1, -c1);

  ull d0 = 0ull, d1 = 0ull;
  ull n0x=0ull, n0y=0ull, n0z=0ull, n0w=0ull;
  ull n1x=0ull, n1y=0ull, n1z=0ull, n1w=0ull;

  const ull* sX = (const ull*)shX; const ull* sY = (const ull*)shY;
  const ull* sZ = (const ull*)shZ; const ull* sW = (const ull*)shW;

  #pragma unroll 4
  for (int ii = 0; ii < ICH/2; ii++){
    ull sx = sX[ii], sy = sY[ii], sz = sZ[ii], sw = sW[ii];
    ull g0 = fma2(qx0, sx, fma2(qy0, sy, fma2(qz0, sz, fma2(qw0, sw, cc0))));
    ull e0 = ex2pair(g0);
    d0  = add2(d0, e0);
    n0x = fma2(sx, e0, n0x); n0y = fma2(sy, e0, n0y);
    n0z = fma2(sz, e0, n0z); n0w = fma2(sw, e0, n0w);
    ull g1 = fma2(qx1, sx, fma2(qy1, sy, fma2(qz1, sz, fma2(qw1, sw, cc1))));
    ull e1 = ex2pair(g1);
    d1  = add2(d1, e1);
    n1x = fma2(sx, e1, n1x); n1y = fma2(sy, e1, n1y);
    n1z = fma2(sz, e1, n1z); n1w = fma2(sw, e1, n1w);
  }

  float2 t2; float4 p;
  t2 = upk2(n0x); p.x = t2.x + t2.y;
  t2 = upk2(n0y); p.y = t2.x + t2.y;
  t2 = upk2(n0z); p.z = t2.x + t2.y;
  t2 = upk2(n0w); p.w = t2.x + t2.y;
  g_pnum[br][ib][j0] = p;
  t2 = upk2(d0);  g_pden[br][ib][j0] = t2.x + t2.y;

  t2 = upk2(n1x); p.x = t2.x + t2.y;
  t2 = upk2(n1y); p.y = t2.x + t2.y;
  t2 = upk2(n1z); p.z = t2.x + t2.y;
  t2 = upk2(n1w); p.w = t2.x + t2.y;
  g_pnum[br][ib][j1] = p;
  t2 = upk2(d1);  g_pden[br][ib][j1] = t2.x + t2.y;
}

// ---------------- k3: combine partials -> Xa, Sa ----------------
__global__ void k3_combine(){
  int idx = blockIdx.x*256 + threadIdx.x;      // 0..16383
  int br = idx >> 13; int j = idx & (NN-1);
  float4 n = make_float4(0.f,0.f,0.f,0.f); float d = 0.f;
  #pragma unroll
  for (int ib = 0; ib < IBLK; ib++){
    float4 p = g_pnum[br][ib][j];
    n.x += p.x; n.y += p.y; n.z += p.z; n.w += p.w;
    d += g_pden[br][ib][j];
  }
  float inv = 1.0f / d;
  float* out = br ? g_Sa : g_Xa;
  out[0*NN+j] = n.x*inv; out[1*NN+j] = n.y*inv;
  out[2*NN+j] = n.z*inv; out[3*NN+j] = n.w*inv;
}

// ---------------- k4: M = W2 @ C; 4 rows/warp, software-pipelined W prefetch ----------------
__global__ void __launch_bounds__(256, 2) k4_gemv(const float* __restrict__ W2){
  __shared__ __align__(16) float Cs[8][KC];
  const int warp = threadIdx.x >> 5, lane = threadIdx.x & 31;
  const int rbase = blockIdx.x*32 + warp*4;
  ull acc[4][8];
  #pragma unroll
  for (int r = 0; r < 4; r++)
    #pragma unroll
    for (int c = 0; c < 8; c++) acc[r][c] = 0ull;

  const float* wrow = &W2[(size_t)rbase*NN];
  int k = lane*4;
  float4 nxt[4];
  #pragma unroll
  for (int r = 0; r < 4; r++)
    nxt[r] = *(const float4*)&wrow[(size_t)r*NN + k];

  for (int kc = 0; kc < NN; kc += KC){
    __syncthreads();
    for (int t = threadIdx.x; t < KC; t += 256){
      float4 a = *(const float4*)&g_Xa[(size_t)(kc + t)*4];
      Cs[0][t]=a.x; Cs[1][t]=a.y; Cs[2][t]=a.z; Cs[3][t]=a.w;
      float4 b = *(const float4*)&g_Sa[(size_t)(kc + t)*4];
      Cs[4][t]=b.x; Cs[5][t]=b.y; Cs[6][t]=b.z; Cs[7][t]=b.w;
    }
    __syncthreads();
    #pragma unroll
    for (int it = 0; it < KC/128; it++){
      // consume current, prefetch next k-step (spans chunk boundaries; W addr is C-independent)
      ull w[4][2];
      #pragma unroll
      for (int r = 0; r < 4; r++){
        w[r][0] = pk2(nxt[r].x, nxt[r].y);
        w[r][1] = pk2(nxt[r].z, nxt[r].w);
      }
      k += 128;
      if (k < NN){
        #pragma unroll
        for (int r = 0; r < 4; r++)
          nxt[r] = *(const float4*)&wrow[(size_t)r*NN + k];
      }
      const int kk = it*128 + lane*4;
      #pragma unroll
      for (int c = 0; c < 8; c++){
        ulonglong2 cv = *(const ulonglong2*)&Cs[c][kk];
        #pragma unroll
        for (int r = 0; r < 4; r++)
          acc[r][c] = fma2(w[r][1], cv.y, fma2(w[r][0], cv.x, acc[r][c]));
      }
    }
  }

  #pragma unroll
  for (int o = 0; o < 32; o++){
    int r = o >> 3, c = o & 7;
    float2 t2 = upk2(acc[r][c]);
    float v = t2.x + t2.y;
    v += __shfl_xor_sync(0xffffffffu, v, 16);
    v += __shfl_xor_sync(0xffffffffu, v, 8);
    v += __shfl_xor_sync(0xffffffffu, v, 4);
    v += __shfl_xor_sync(0xffffffffu, v, 2);
    v += __shfl_xor_sync(0xffffffffu, v, 1);
    if (lane == o){
      int row = rbase + r;
      if (c < 4) g_Mx[row*4 + c] = v;
      else       g_Ms[row*4 + (c-4)] = v;
    }
  }
}

// ---------------- k5: gates + sinusoid + dual 3x3(W=1 -> 1D vertical) conv ----------------
__global__ void k5_conv(const float* __restrict__ X, const float* __restrict__ S,
                        const float* __restrict__ wx, const float* __restrict__ bx,
                        const float* __restrict__ ws, const float* __restrict__ bs,
                        float* __restrict__ out){
  __shared__ float in_s[2][8][258];
  __shared__ float wmid[2][8][8][3];
  __shared__ float bias[2][8];
  __shared__ float sins[258];
  const int t = threadIdx.x;
  const int n0 = blockIdx.x*256;

  for (int idx = t; idx < 384; idx += 256){
    int b = idx/192, rem = idx%192;
    int co = rem/24, ci = (rem%24)/3, kh = rem%3;
    const float* w = b ? ws : wx;
    wmid[b][co][ci][kh] = w[((co*8 + ci)*3 + kh)*3 + 1];
  }
  if (t < 16) bias[t>>3][t&7] = (t < 8) ? bx[t] : bs[t-8];
  for (int col = t; col < 258; col += 256)
    sins[col] = (float)sin((double)(n0 + col - 1));
  __syncthreads();

  for (int idx = t; idx < 2*8*258; idx += 256){
    int b = idx/(8*258); int rem = idx%(8*258);
    int ci = rem/258, col = rem%258;
    int n = n0 + col - 1;
    float v = 0.f;
    if (n >= 0 && n < NN){
      if (b == 0){
        v = (ci < 4) ? g_Mx[ci*NN + n]*X[ci*NN + n] : X[(ci-4)*NN + n];
      } else {
        v = (ci < 4) ? g_Ms[ci*NN + n]*X[ci*NN + n] : S[(ci-4)*NN + n];
        v += sins[col];
      }
    }
    in_s[b][ci][col] = v;
  }
  __syncthreads();

  const int n = n0 + t;
  #pragma unroll
  for (int b = 0; b < 2; b++){
    #pragma unroll
    for (int co = 0; co < 8; co++){
      float a = bias[b][co];
      #pragma unroll
      for (int ci = 0; ci < 8; ci++){
        a = fmaf(wmid[b][co][ci][0], in_s[b][ci][t  ], a);
        a = fmaf(wmid[b][co][ci][1], in_s[b][ci][t+1], a);
        a = fmaf(wmid[b][co][ci][2], in_s[b][ci][t+2], a);
      }
      out[(size_t)b*8*NN + (size_t)co*NN + n] = a;
    }
  }
}

// ---------------- launch ----------------
extern "C" void kernel_launch(void* const* d_in, const int* in_sizes, int n_in,
                              void* d_out, int out_size){
  (void)in_sizes; (void)n_in; (void)out_size;
  const float* X   = (const float*)d_in[0];
  const float* S   = (const float*)d_in[1];
  const float* W1x = (const float*)d_in[2];
  const float* W1s = (const float*)d_in[3];
  const float* W2  = (const float*)d_in[4];
  const float* cwx = (const float*)d_in[5];
  const float* cbx = (const float*)d_in[6];
  const float* cws = (const float*)d_in[7];
  const float* cbs = (const float*)d_in[8];
  float* out = (float*)d_out;

  k1_embed  <<<NB1, 256>>>(X, S, W1x, W1s);
  k2_attn   <<<dim3(JBLK, IBLK, 2), 256>>>();
  k3_combine<<<64, 256>>>();
  k4_gemv   <<<NN/32, 256>>>(W2);
  k5_conv   <<<NN/256, 256>>>(X, S, cwx, cbx, cws, cbs, out);
}

// round 6
// speedup vs baseline: 1.0885x; 1.0670x over previous
#include <cuda_runtime.h>
#include <cmath>

#define NN 8192
#define NB1 32
#define IBLK 8
#define ICH (NN/IBLK)      /* 1024 */
#define JBLK 16
#define JPB (NN/JBLK)      /* 512  */
#define KC 1024
#define PFD 512            /* L2 prefetch distance in floats (4 iters ahead) */

typedef unsigned long long ull;

// ---------------- scratch (__device__ globals: no allocs allowed) ----------------
__device__ __align__(16) float4 g_XeT[NN];
__device__ __align__(16) float4 g_SeT[NN];
__device__ float g_bmax[NB1];
__device__ __align__(16) float4 g_pnum[2][IBLK][NN];
__device__ float g_pden[2][IBLK][NN];
__device__ __align__(16) float g_Xa[4*NN];
__device__ __align__(16) float g_Sa[4*NN];
__device__ __align__(16) float g_Mx[4*NN];
__device__ __align__(16) float g_Ms[4*NN];

// ---------------- small PTX helpers ----------------
__device__ __forceinline__ ull pk2(float lo, float hi){ ull r; asm("mov.b64 %0, {%1, %2};" : "=l"(r) : "f"(lo), "f"(hi)); return r; }
__device__ __forceinline__ float2 upk2(ull v){ float2 f; asm("mov.b64 {%0, %1}, %2;" : "=f"(f.x), "=f"(f.y) : "l"(v)); return f; }
__device__ __forceinline__ ull fma2(ull a, ull b, ull c){ ull d; asm("fma.rn.f32x2 %0, %1, %2, %3;" : "=l"(d) : "l"(a), "l"(b), "l"(c)); return d; }
__device__ __forceinline__ ull add2(ull a, ull b){ ull d; asm("add.rn.f32x2 %0, %1, %2;" : "=l"(d) : "l"(a), "l"(b)); return d; }
__device__ __forceinline__ void pfL2(const void* p){ asm volatile("prefetch.global.L2 [%0];" :: "l"(p)); }
__device__ __forceinline__ ull ex2pair(ull g){
  ull e;
  asm("{\n\t.reg .f32 lo, hi;\n\t"
      "mov.b64 {lo, hi}, %1;\n\t"
      "ex2.approx.ftz.f32 lo, lo;\n\t"
      "ex2.approx.ftz.f32 hi, hi;\n\t"
      "mov.b64 %0, {lo, hi};\n\t}" : "=l"(e) : "l"(g));
  return e;
}

// ---------------- k1: Xe = W1x@S, Se = W1s@X, per-column norms, block max ----------------
__global__ void k1_embed(const float* __restrict__ X, const float* __restrict__ S,
                         const float* __restrict__ W1x, const float* __restrict__ W1s){
  int j = blockIdx.x*blockDim.x + threadIdx.x;
  float s0=S[j], s1=S[NN+j], s2=S[2*NN+j], s3=S[3*NN+j];
  float x0=X[j], x1=X[NN+j], x2=X[2*NN+j], x3=X[3*NN+j];
  float4 xe, se;
  xe.x = W1x[ 0]*s0 + W1x[ 1]*s1 + W1x[ 2]*s2 + W1x[ 3]*s3;
  xe.y = W1x[ 4]*s0 + W1x[ 5]*s1 + W1x[ 6]*s2 + W1x[ 7]*s3;
  xe.z = W1x[ 8]*s0 + W1x[ 9]*s1 + W1x[10]*s2 + W1x[11]*s3;
  xe.w = W1x[12]*s0 + W1x[13]*s1 + W1x[14]*s2 + W1x[15]*s3;
  se.x = W1s[ 0]*x0 + W1s[ 1]*x1 + W1s[ 2]*x2 + W1s[ 3]*x3;
  se.y = W1s[ 4]*x0 + W1s[ 5]*x1 + W1s[ 6]*x2 + W1s[ 7]*x3;
  se.z = W1s[ 8]*x0 + W1s[ 9]*x1 + W1s[10]*x2 + W1s[11]*x3;
  se.w = W1s[12]*x0 + W1s[13]*x1 + W1s[14]*x2 + W1s[15]*x3;
  g_XeT[j] = xe; g_SeT[j] = se;
  float nx = xe.x*xe.x + xe.y*xe.y + xe.z*xe.z + xe.w*xe.w;
  float ns = se.x*se.x + se.y*se.y + se.z*se.z + se.w*se.w;
  float m = sqrtf(fmaxf(nx, ns));
  __shared__ float red[256];
  red[threadIdx.x] = m; __syncthreads();
  for (int s = 128; s > 0; s >>= 1){
    if (threadIdx.x < s) red[threadIdx.x] = fmaxf(red[threadIdx.x], red[threadIdx.x+s]);
    __syncthreads();
  }
  if (threadIdx.x == 0) g_bmax[blockIdx.x] = red[0];
}

// ---------------- k2: rank-4 streaming softmax-attention partials (f32x2 over i-pairs) ----------------
__global__ void k2_attn(){
  const int jb = blockIdx.x, ib = blockIdx.y, br = blockIdx.z;
  const float4* __restrict__ E = br ? g_SeT : g_XeT;
  __shared__ float shX[ICH], shY[ICH], shZ[ICH], shW[ICH];

  float Nmax = 0.f;
  #pragma unroll
  for (int b = 0; b < NB1; b++) Nmax = fmaxf(Nmax, g_bmax[b]);

  const int ibase = ib*ICH;
  for (int t = threadIdx.x; t < ICH; t += blockDim.x){
    float4 v = E[ibase + t];
    shX[t]=v.x; shY[t]=v.y; shZ[t]=v.z; shW[t]=v.w;
  }
  __syncthreads();

  const float L2E = 1.4426950408889634f;
  const int j0 = jb*JPB + threadIdx.x;
  const int j1 = j0 + 256;
  float4 q0 = E[j0], q1 = E[j1];
  float c0 = sqrtf(q0.x*q0.x+q0.y*q0.y+q0.z*q0.z+q0.w*q0.w) * Nmax * L2E;
  float c1 = sqrtf(q1.x*q1.x+q1.y*q1.y+q1.z*q1.z+q1.w*q1.w) * Nmax * L2E;
  ull qx0 = pk2(q0.x*L2E, q0.x*L2E), qy0 = pk2(q0.y*L2E, q0.y*L2E);
  ull qz0 = pk2(q0.z*L2E, q0.z*L2E), qw0 = pk2(q0.w*L2E, q0.w*L2E);
  ull qx1 = pk2(q1.x*L2E, q1.x*L2E), qy1 = pk2(q1.y*L2E, q1.y*L2E);
  ull qz1 = pk2(q1.z*L2E, q1.z*L2E), qw1 = pk2(q1.w*L2E, q1.w*L2E);
  ull cc0 = pk2(-c0, -c0), cc1 = pk2(-c1, -c1);

  ull d0 = 0ull, d1 = 0ull;
  ull n0x=0ull, n0y=0ull, n0z=0ull, n0w=0ull;
  ull n1x=0ull, n1y=0ull, n1z=0ull, n1w=0ull;

  const ull* sX = (const ull*)shX; const ull* sY = (const ull*)shY;
  const ull* sZ = (const ull*)shZ; const ull* sW = (const ull*)shW;

  #pragma unroll 4
  for (int ii = 0; ii < ICH/2; ii++){
    ull sx = sX[ii], sy = sY[ii], sz = sZ[ii], sw = sW[ii];
    ull g0 = fma2(qx0, sx, fma2(qy0, sy, fma2(qz0, sz, fma2(qw0, sw, cc0))));
    ull e0 = ex2pair(g0);
    d0  = add2(d0, e0);
    n0x = fma2(sx, e0, n0x); n0y = fma2(sy, e0, n0y);
    n0z = fma2(sz, e0, n0z); n0w = fma2(sw, e0, n0w);
    ull g1 = fma2(qx1, sx, fma2(qy1, sy, fma2(qz1, sz, fma2(qw1, sw, cc1))));
    ull e1 = ex2pair(g1);
    d1  = add2(d1, e1);
    n1x = fma2(sx, e1, n1x); n1y = fma2(sy, e1, n1y);
    n1z = fma2(sz, e1, n1z); n1w = fma2(sw, e1, n1w);
  }

  float2 t2; float4 p;
  t2 = upk2(n0x); p.x = t2.x + t2.y;
  t2 = upk2(n0y); p.y = t2.x + t2.y;
  t2 = upk2(n0z); p.z = t2.x + t2.y;
  t2 = upk2(n0w); p.w = t2.x + t2.y;
  g_pnum[br][ib][j0] = p;
  t2 = upk2(d0);  g_pden[br][ib][j0] = t2.x + t2.y;

  t2 = upk2(n1x); p.x = t2.x + t2.y;
  t2 = upk2(n1y); p.y = t2.x + t2.y;
  t2 = upk2(n1z); p.z = t2.x + t2.y;
  t2 = upk2(n1w); p.w = t2.x + t2.y;
  g_pnum[br][ib][j1] = p;
  t2 = upk2(d1);  g_pden[br][ib][j1] = t2.x + t2.y;
}

// ---------------- k3: combine partials -> Xa, Sa ----------------
__global__ void k3_combine(){
  int idx = blockIdx.x*256 + threadIdx.x;      // 0..16383
  int br = idx >> 13; int j = idx & (NN-1);
  float4 n = make_float4(0.f,0.f,0.f,0.f); float d = 0.f;
  #pragma unroll
  for (int ib = 0; ib < IBLK; ib++){
    float4 p = g_pnum[br][ib][j];
    n.x += p.x; n.y += p.y; n.z += p.z; n.w += p.w;
    d += g_pden[br][ib][j];
  }
  float inv = 1.0f / d;
  float* out = br ? g_Sa : g_Xa;
  out[0*NN+j] = n.x*inv; out[1*NN+j] = n.y*inv;
  out[2*NN+j] = n.z*inv; out[3*NN+j] = n.w*inv;
}

// ---------------- k4: M = W2 @ C; 4 rows/warp + zero-register L2 prefetch ----------------
__global__ void __launch_bounds__(256, 2) k4_gemv(const float* __restrict__ W2){
  __shared__ __align__(16) float Cs[8][KC];
  const int warp = threadIdx.x >> 5, lane = threadIdx.x & 31;
  const int rbase = blockIdx.x*32 + warp*4;
  ull acc[4][8];
  #pragma unroll
  for (int r = 0; r < 4; r++)
    #pragma unroll
    for (int c = 0; c < 8; c++) acc[r][c] = 0ull;

  const float* wrow = &W2[(size_t)rbase*NN];

  for (int kc = 0; kc < NN; kc += KC){
    __syncthreads();
    for (int t = threadIdx.x; t < KC; t += 256){
      float4 a = *(const float4*)&g_Xa[(size_t)(kc + t)*4];
      Cs[0][t]=a.x; Cs[1][t]=a.y; Cs[2][t]=a.z; Cs[3][t]=a.w;
      float4 b = *(const float4*)&g_Sa[(size_t)(kc + t)*4];
      Cs[4][t]=b.x; Cs[5][t]=b.y; Cs[6][t]=b.z; Cs[7][t]=b.w;
    }
    __syncthreads();
    for (int kk = lane*4; kk < KC; kk += 128){
      // zero-register latency hiding: pull the k+PFD lines into L2 ahead of use
      const int kpf = kc + kk + PFD;
      if (kpf < NN){
        pfL2(&wrow[kpf]);
        pfL2(&wrow[(size_t)1*NN + kpf]);
        pfL2(&wrow[(size_t)2*NN + kpf]);
        pfL2(&wrow[(size_t)3*NN + kpf]);
      }
      ull w[4][2];
      #pragma unroll
      for (int r = 0; r < 4; r++){
        float4 a = *(const float4*)&wrow[(size_t)r*NN + kc + kk];
        w[r][0] = pk2(a.x, a.y); w[r][1] = pk2(a.z, a.w);
      }
      #pragma unroll
      for (int c = 0; c < 8; c++){
        ulonglong2 cv = *(const ulonglong2*)&Cs[c][kk];
        #pragma unroll
        for (int r = 0; r < 4; r++)
          acc[r][c] = fma2(w[r][1], cv.y, fma2(w[r][0], cv.x, acc[r][c]));
      }
    }
  }

  #pragma unroll
  for (int o = 0; o < 32; o++){
    int r = o >> 3, c = o & 7;
    float2 t2 = upk2(acc[r][c]);
    float v = t2.x + t2.y;
    v += __shfl_xor_sync(0xffffffffu, v, 16);
    v += __shfl_xor_sync(0xffffffffu, v, 8);
    v += __shfl_xor_sync(0xffffffffu, v, 4);
    v += __shfl_xor_sync(0xffffffffu, v, 2);
    v += __shfl_xor_sync(0xffffffffu, v, 1);
    if (lane == o){
      int row = rbase + r;
      if (c < 4) g_Mx[row*4 + c] = v;
      else       g_Ms[row*4 + (c-4)] = v;
    }
  }
}

// ---------------- k5: gates + sinusoid + dual 3x3(W=1 -> 1D vertical) conv ----------------
__global__ void k5_conv(const float* __restrict__ X, const float* __restrict__ S,
                        const float* __restrict__ wx, const float* __restrict__ bx,
                        const float* __restrict__ ws, const float* __restrict__ bs,
                        float* __restrict__ out){
  __shared__ float in_s[2][8][258];
  __shared__ float wmid[2][8][8][3];
  __shared__ float bias[2][8];
  __shared__ float sins[258];
  const int t = threadIdx.x;
  const int n0 = blockIdx.x*256;

  for (int idx = t; idx < 384; idx += 256){
    int b = idx/192, rem = idx%192;
    int co = rem/24, ci = (rem%24)/3, kh = rem%3;
    const float* w = b ? ws : wx;
    wmid[b][co][ci][kh] = w[((co*8 + ci)*3 + kh)*3 + 1];
  }
  if (t < 16) bias[t>>3][t&7] = (t < 8) ? bx[t] : bs[t-8];
  for (int col = t; col < 258; col += 256)
    sins[col] = (float)sin((double)(n0 + col - 1));
  __syncthreads();

  for (int idx = t; idx < 2*8*258; idx += 256){
    int b = idx/(8*258); int rem = idx%(8*258);
    int ci = rem/258, col = rem%258;
    int n = n0 + col - 1;
    float v = 0.f;
    if (n >= 0 && n < NN){
      if (b == 0){
        v = (ci < 4) ? g_Mx[ci*NN + n]*X[ci*NN + n] : X[(ci-4)*NN + n];
      } else {
        v = (ci < 4) ? g_Ms[ci*NN + n]*X[ci*NN + n] : S[(ci-4)*NN + n];
        v += sins[col];
      }
    }
    in_s[b][ci][col] = v;
  }
  __syncthreads();

  const int n = n0 + t;
  #pragma unroll
  for (int b = 0; b < 2; b++){
    #pragma unroll
    for (int co = 0; co < 8; co++){
      float a = bias[b][co];
      #pragma unroll
      for (int ci = 0; ci < 8; ci++){
        a = fmaf(wmid[b][co][ci][0], in_s[b][ci][t  ], a);
        a = fmaf(wmid[b][co][ci][1], in_s[b][ci][t+1], a);
        a = fmaf(wmid[b][co][ci][2], in_s[b][ci][t+2], a);
      }
      out[(size_t)b*8*NN + (size_t)co*NN + n] = a;
    }
  }
}

// ---------------- launch ----------------
extern "C" void kernel_launch(void* const* d_in, const int* in_sizes, int n_in,
                              void* d_out, int out_size){
  (void)in_sizes; (void)n_in; (void)out_size;
  const float* X   = (const float*)d_in[0];
  const float* S   = (const float*)d_in[1];
  const float* W1x = (const float*)d_in[2];
  const float* W1s = (const float*)d_in[3];
  const float* W2  = (const float*)d_in[4];
  const float* cwx = (const float*)d_in[5];
  const float* cbx = (const float*)d_in[6];
  const float* cws = (const float*)d_in[7];
  const float* cbs = (const float*)d_in[8];
  float* out = (float*)d_out;

  k1_embed  <<<NB1, 256>>>(X, S, W1x, W1s);
  k2_attn   <<<dim3(JBLK, IBLK, 2), 256>>>();
  k3_combine<<<64, 256>>>();
  k4_gemv   <<<NN/32, 256>>>(W2);
  k5_conv   <<<NN/256, 256>>>(X, S, cwx, cbx, cws, cbs, out);
}